// round 15
// baseline (speedup 1.0000x reference)
#include <cuda_runtime.h>
#include <cuda_fp16.h>
#include <math.h>
#include <float.h>

#define N_NODES 100000
#define N_EDGES 1600000
#define FDIM 64
#define N_GRAPHS 64
#define EPSV 1e-5f

#define SCAN_BLOCKS 98   // ceil(100000/1024)

typedef unsigned long long u64;
typedef unsigned int u32;

// ---------------- scratch (device globals; no allocation allowed) ----------
__device__ float2 g_degcnt[N_NODES];             // {weighted deg, count}
__device__ float g_dis[N_NODES];                 // deg^{-1/2}
__device__ int   g_cnt[N_NODES];                 // per-dst edge count (int)
__device__ int   g_rowptr[N_NODES + 1];          // CSR row pointers (by dst)
__device__ int   g_fill[N_NODES];                // running fill cursors
__device__ int   g_bsum[128];                    // block sums for scan
__device__ int2  g_epack[N_EDGES];               // CSR payload: {src, bits(norm)}
__device__ __half2 g_xh[N_NODES * FDIM / 2];     // fp16 copy of x
__device__ __half2 g_h16[3][N_NODES * FDIM / 2]; // h1, h2, h3 (fp16)
__device__ float g_out[N_NODES * FDIM];          // TAGConv output
__device__ float g_sum[N_GRAPHS * FDIM];         // per-graph feature sums
__device__ float g_sumsq[N_GRAPHS * FDIM];       // per-graph feature sq-sums

// ---------------- fused: zero scratch + x -> fp16 copy ---------------------
__global__ __launch_bounds__(1024) void zx_kernel(const float* __restrict__ x,
                                                  float* __restrict__ flat) {
    int i = blockIdx.x * blockDim.x + threadIdx.x;
    if (i < N_NODES) g_degcnt[i] = make_float2(0.f, 0.f);
    if (i < N_GRAPHS * FDIM) { g_sum[i] = 0.f; g_sumsq[i] = 0.f; }
    if (i < N_GRAPHS * 2 * FDIM) flat[i] = 0.f;
    const float2* x2 = (const float2*)x;
    int total = SCAN_BLOCKS * 1024;
    for (int j = i; j < N_NODES * FDIM / 2; j += total)
        g_xh[j] = __float22half2_rn(x2[j]);
}

// ---------------- degree + histogram: one vector red per edge --------------
__global__ void deg_hist_kernel(const int* __restrict__ dst, const float* __restrict__ ew) {
    int e = blockIdx.x * blockDim.x + threadIdx.x;
    if (e < N_EDGES) {
        int d = dst[e];
        float w = ew[e];
        float* addr = (float*)&g_degcnt[d];
        asm volatile("red.global.add.v2.f32 [%0], {%1, %2};"
                     :: "l"(addr), "f"(w), "f"(1.0f) : "memory");
    }
}

// ---------------- fused: degcnt -> dis + int cnt + scan stage A ------------
__global__ __launch_bounds__(1024) void dis_scanA_kernel() {
    __shared__ int sd[1024];
    int tid = threadIdx.x;
    int i = blockIdx.x * 1024 + tid;
    int c = 0;
    if (i < N_NODES) {
        float2 dc = g_degcnt[i];
        g_dis[i] = (dc.x > 0.f) ? rsqrtf(dc.x) : 0.f;
        c = (int)(dc.y + 0.5f);
        g_cnt[i] = c;
    }
    sd[tid] = c;
    __syncthreads();
    for (int s = 512; s > 0; s >>= 1) {
        if (tid < s) sd[tid] += sd[tid + s];
        __syncthreads();
    }
    if (tid == 0) g_bsum[blockIdx.x] = sd[0];
}

// ---------------- scan stage B: exclusive scan of block sums ---------------
__global__ void scanB_kernel() {
    __shared__ int sb[128];
    int tid = threadIdx.x;
    sb[tid] = (tid < SCAN_BLOCKS) ? g_bsum[tid] : 0;
    __syncthreads();
    if (tid == 0) {
        int run = 0;
        for (int i = 0; i < SCAN_BLOCKS; i++) { int v = sb[i]; sb[i] = run; run += v; }
    }
    __syncthreads();
    if (tid < SCAN_BLOCKS) g_bsum[tid] = sb[tid];
}

// ---------------- scan stage C: per-element exclusive scan -> rowptr/fill --
__global__ __launch_bounds__(1024) void scanC_kernel() {
    __shared__ int sd[1024];
    int tid = threadIdx.x;
    int i = blockIdx.x * 1024 + tid;
    int v = (i < N_NODES) ? g_cnt[i] : 0;
    sd[tid] = v;
    __syncthreads();
    for (int off = 1; off < 1024; off <<= 1) {
        int tv = 0;
        if (tid >= off) tv = sd[tid - off];
        __syncthreads();
        sd[tid] += tv;
        __syncthreads();
    }
    int excl = sd[tid] - v + g_bsum[blockIdx.x];
    if (i < N_NODES) { g_rowptr[i] = excl; g_fill[i] = excl; }
    if (i == N_NODES - 1) g_rowptr[N_NODES] = excl + v;
}

// ---------------- CSR fill: compute norm + scatter edge payload ------------
__global__ void fill_kernel(const int* __restrict__ src, const int* __restrict__ dst,
                            const float* __restrict__ ew) {
    int e = blockIdx.x * blockDim.x + threadIdx.x;
    if (e < N_EDGES) {
        int s = src[e];
        int d = dst[e];
        float nrm = g_dis[s] * ew[e] * g_dis[d];
        int pos = atomicAdd(&g_fill[d], 1);
        g_epack[pos] = make_int2(s, __float_as_int(nrm));
    }
}

// ---------------- hop: hout[n] = sum_{j in row(n)} norm_j * hin[src_j] -----
// One warp per node; lane owns a half2 pair (128B coalesced row gather).
// Meta double-buffered (next 32-edge batch prefetched before processing the
// current one) and 8-wide unrolled gathers -> MLP ~8, meta latency hidden.
__global__ __launch_bounds__(256) void hop_kernel(const __half2* __restrict__ hin2,
                                                  __half2* __restrict__ hout2) {
    const unsigned FULL = 0xffffffffu;
    int warp = threadIdx.x >> 5;
    int lane = threadIdx.x & 31;
    int node = (blockIdx.x << 3) + warp;          // grid covers exactly 100000
    int lo = g_rowptr[node];
    int hi = g_rowptr[node + 1];
    float2 acc = make_float2(0.f, 0.f);

    int2 e = make_int2(0, 0);
    if (lo + lane < hi) e = g_epack[lo + lane];

    for (int base = lo; base < hi; base += 32) {
        int n = hi - base; if (n > 32) n = 32;
        // prefetch next meta batch (hides L2 latency behind current batch)
        int2 enext = make_int2(0, 0);
        int nb = base + 32;
        if (nb + lane < hi) enext = g_epack[nb + lane];

        int j = 0;
        for (; j + 8 <= n; j += 8) {
            int s0 = __shfl_sync(FULL, e.x, j);
            int s1 = __shfl_sync(FULL, e.x, j + 1);
            int s2 = __shfl_sync(FULL, e.x, j + 2);
            int s3 = __shfl_sync(FULL, e.x, j + 3);
            int s4 = __shfl_sync(FULL, e.x, j + 4);
            int s5 = __shfl_sync(FULL, e.x, j + 5);
            int s6 = __shfl_sync(FULL, e.x, j + 6);
            int s7 = __shfl_sync(FULL, e.x, j + 7);
            float w0 = __int_as_float(__shfl_sync(FULL, e.y, j));
            float w1 = __int_as_float(__shfl_sync(FULL, e.y, j + 1));
            float w2 = __int_as_float(__shfl_sync(FULL, e.y, j + 2));
            float w3 = __int_as_float(__shfl_sync(FULL, e.y, j + 3));
            float w4 = __int_as_float(__shfl_sync(FULL, e.y, j + 4));
            float w5 = __int_as_float(__shfl_sync(FULL, e.y, j + 5));
            float w6 = __int_as_float(__shfl_sync(FULL, e.y, j + 6));
            float w7 = __int_as_float(__shfl_sync(FULL, e.y, j + 7));
            __half2 v0 = hin2[s0 * 32 + lane];
            __half2 v1 = hin2[s1 * 32 + lane];
            __half2 v2 = hin2[s2 * 32 + lane];
            __half2 v3 = hin2[s3 * 32 + lane];
            __half2 v4 = hin2[s4 * 32 + lane];
            __half2 v5 = hin2[s5 * 32 + lane];
            __half2 v6 = hin2[s6 * 32 + lane];
            __half2 v7 = hin2[s7 * 32 + lane];
            float2 f0 = __half22float2(v0);
            float2 f1 = __half22float2(v1);
            float2 f2 = __half22float2(v2);
            float2 f3 = __half22float2(v3);
            float2 f4 = __half22float2(v4);
            float2 f5 = __half22float2(v5);
            float2 f6 = __half22float2(v6);
            float2 f7 = __half22float2(v7);
            acc.x = fmaf(w0, f0.x, acc.x); acc.y = fmaf(w0, f0.y, acc.y);
            acc.x = fmaf(w1, f1.x, acc.x); acc.y = fmaf(w1, f1.y, acc.y);
            acc.x = fmaf(w2, f2.x, acc.x); acc.y = fmaf(w2, f2.y, acc.y);
            acc.x = fmaf(w3, f3.x, acc.x); acc.y = fmaf(w3, f3.y, acc.y);
            acc.x = fmaf(w4, f4.x, acc.x); acc.y = fmaf(w4, f4.y, acc.y);
            acc.x = fmaf(w5, f5.x, acc.x); acc.y = fmaf(w5, f5.y, acc.y);
            acc.x = fmaf(w6, f6.x, acc.x); acc.y = fmaf(w6, f6.y, acc.y);
            acc.x = fmaf(w7, f7.x, acc.x); acc.y = fmaf(w7, f7.y, acc.y);
        }
        for (; j < n; j++) {
            int s = __shfl_sync(FULL, e.x, j);
            float w = __int_as_float(__shfl_sync(FULL, e.y, j));
            float2 f = __half22float2(hin2[s * 32 + lane]);
            acc.x = fmaf(w, f.x, acc.x); acc.y = fmaf(w, f.y, acc.y);
        }
        e = enext;
    }
    hout2[node * 32 + lane] = __float22half2_rn(acc);
}

// ---------------- HMMA GEMM: out = [xh|h1|h2|h3](fp16) @ W(fp16) + b -------
#define BPITCH 264
__global__ __launch_bounds__(256) void gemm_hmma_kernel(
        const __half* __restrict__ xh,
        const __half* __restrict__ h1, const __half* __restrict__ h2,
        const __half* __restrict__ h3,
        const float* __restrict__ W, const float* __restrict__ b,
        float* __restrict__ out) {
    __shared__ __align__(16) __half Bst[FDIM * BPITCH];   // [n][k], k=0..255
    int t = threadIdx.x;

    for (int i = t; i < 256 * FDIM; i += 256) {
        int k = i >> 6, n = i & 63;
        Bst[n * BPITCH + k] = __float2half(W[i]);
    }
    __syncthreads();

    int warp = t >> 5, lane = t & 31;
    int g = lane >> 2, tq = lane & 3;
    int m0 = blockIdx.x * 128 + warp * 16;
    int rA = m0 + g;
    int rB = m0 + g + 8;
    bool okA = rA < N_NODES;
    bool okB = rB < N_NODES;

    float acc[8][4];
#pragma unroll
    for (int nt = 0; nt < 8; nt++)
#pragma unroll
        for (int c = 0; c < 4; c++) acc[nt][c] = 0.f;

    const __half* Hs[4] = {xh, h1, h2, h3};

#pragma unroll
    for (int kb = 0; kb < 4; kb++) {
        const __half* H = Hs[kb];
        const __half* rowa = H + (size_t)rA * FDIM;
        const __half* rowb = H + (size_t)rB * FDIM;
#pragma unroll
        for (int jc = 0; jc < 4; jc++) {
            int kl = jc * 16 + tq * 2;
            unsigned a0 = okA ? *(const unsigned*)&rowa[kl]     : 0u;
            unsigned a2 = okA ? *(const unsigned*)&rowa[kl + 8] : 0u;
            unsigned a1 = okB ? *(const unsigned*)&rowb[kl]     : 0u;
            unsigned a3 = okB ? *(const unsigned*)&rowb[kl + 8] : 0u;
            int kg = kb * 64 + kl;
#pragma unroll
            for (int nt = 0; nt < 8; nt++) {
                int n = nt * 8 + g;
                unsigned b0 = *(const unsigned*)&Bst[n * BPITCH + kg];
                unsigned b1 = *(const unsigned*)&Bst[n * BPITCH + kg + 8];
                asm volatile(
                    "mma.sync.aligned.m16n8k16.row.col.f32.f16.f16.f32 "
                    "{%0,%1,%2,%3}, {%4,%5,%6,%7}, {%8,%9}, {%0,%1,%2,%3};"
                    : "+f"(acc[nt][0]), "+f"(acc[nt][1]),
                      "+f"(acc[nt][2]), "+f"(acc[nt][3])
                    : "r"(a0), "r"(a1), "r"(a2), "r"(a3), "r"(b0), "r"(b1));
            }
        }
    }

#pragma unroll
    for (int nt = 0; nt < 8; nt++) {
        int col = nt * 8 + tq * 2;
        float2 bb = *(const float2*)&b[col];
        if (okA)
            *(float2*)&out[(size_t)rA * FDIM + col] =
                make_float2(acc[nt][0] + bb.x, acc[nt][1] + bb.y);
        if (okB)
            *(float2*)&out[(size_t)rB * FDIM + col] =
                make_float2(acc[nt][2] + bb.x, acc[nt][3] + bb.y);
    }
}

// ---------------- graph range lookup (batch is sorted) ---------------------
__device__ __forceinline__ void graph_range(const int* __restrict__ batch, int g,
                                            int& lo, int& hi) {
    int a = 0, bb = N_NODES;
    while (a < bb) { int m = (a + bb) >> 1; if (batch[m] < g) a = m + 1; else bb = m; }
    lo = a;
    bb = N_NODES;
    while (a < bb) { int m = (a + bb) >> 1; if (batch[m] < g + 1) a = m + 1; else bb = m; }
    hi = a;
}

#define NCHUNK 16   // chunks per graph for stats/apply

// ---------------- NP1: per-chunk sum / sumsq partials ----------------------
__global__ __launch_bounds__(256) void stats_kernel(const float* __restrict__ outv,
                                                    const int* __restrict__ batch) {
    int g = blockIdx.x / NCHUNK;
    int q = blockIdx.x % NCHUNK;
    int lo, hi;
    graph_range(batch, g, lo, hi);
    int cnt = hi - lo;
    int qlo = lo + (int)(((long)cnt * q) / NCHUNK);
    int qhi = lo + (int)(((long)cnt * (q + 1)) / NCHUNK);

    int f = threadIdx.x & 63;
    int r = threadIdx.x >> 6;
    float s = 0.f, sq = 0.f;
    for (int n = qlo + r; n < qhi; n += 4) {
        float o = outv[(size_t)n * FDIM + f];
        s += o;
        sq = fmaf(o, o, sq);
    }
    __shared__ float red[256];
    red[threadIdx.x] = s;
    __syncthreads();
    if (r == 0) {
        float t = red[f] + red[64 + f] + red[128 + f] + red[192 + f];
        atomicAdd(&g_sum[g * FDIM + f], t);
    }
    __syncthreads();
    red[threadIdx.x] = sq;
    __syncthreads();
    if (r == 0) {
        float t = red[f] + red[64 + f] + red[128 + f] + red[192 + f];
        atomicAdd(&g_sumsq[g * FDIM + f], t);
    }
}

// ---------------- NP2: apply (inline finalize) + ReLU + pooled partials ----
__global__ __launch_bounds__(256) void apply_pool_kernel(
        const float* __restrict__ outv, const float* __restrict__ x,
        const int* __restrict__ batch,
        const float* __restrict__ gw, const float* __restrict__ gb,
        const float* __restrict__ gms,
        float* __restrict__ hemb, float* __restrict__ flat) {
    int g = blockIdx.x / NCHUNK;
    int q = blockIdx.x % NCHUNK;
    int lo, hi;
    graph_range(batch, g, lo, hi);
    int cnt = hi - lo;
    float invc = 1.0f / fmaxf((float)cnt, 1.0f);
    int qlo = lo + (int)(((long)cnt * q) / NCHUNK);
    int qhi = lo + (int)(((long)cnt * (q + 1)) / NCHUNK);

    int f = threadIdx.x & 63;
    int r = threadIdx.x >> 6;

    // inline finalize: mc and a from global stats (stats_kernel completed)
    float mean = g_sum[g * FDIM + f] * invc;
    float mc = mean * gms[f];
    float var = g_sumsq[g * FDIM + f] * invc - 2.f * mc * mean + mc * mc;
    float a = gw[f] * rsqrtf(var + EPSV);
    float bf = gb[f];

    float ps = 0.f, pm = 0.f;   // relu output >= 0 -> 0 is a safe max identity
    for (int n = qlo + r; n < qhi; n += 4) {
        float c = outv[(size_t)n * FDIM + f] - mc;
        float hn = fmaf(a, c, bf);
        float he = fmaxf(hn + x[(size_t)n * FDIM + f], 0.f);
        hemb[(size_t)n * FDIM + f] = he;
        ps += he;
        pm = fmaxf(pm, he);
    }
    __shared__ float red[256];
    red[threadIdx.x] = ps;
    __syncthreads();
    if (r == 0) {
        float t = red[f] + red[64 + f] + red[128 + f] + red[192 + f];
        atomicAdd(&flat[g * 2 * FDIM + f], t * invc);
    }
    __syncthreads();
    red[threadIdx.x] = pm;
    __syncthreads();
    if (r == 0) {
        float t = fmaxf(fmaxf(red[f], red[64 + f]), fmaxf(red[128 + f], red[192 + f]));
        atomicMax((u32*)&flat[g * 2 * FDIM + FDIM + f], __float_as_uint(t));
    }
}

// ---------------------------------------------------------------------------
extern "C" void kernel_launch(void* const* d_in, const int* in_sizes, int n_in,
                              void* d_out, int out_size) {
    const float* x     = (const float*)d_in[0];
    const int*   ei    = (const int*)d_in[1];
    const int*   batch = (const int*)d_in[2];
    const float* ew    = (const float*)d_in[3];
    const float* W     = (const float*)d_in[4];
    const float* b     = (const float*)d_in[5];
    const float* gw    = (const float*)d_in[6];
    const float* gb    = (const float*)d_in[7];
    const float* gms   = (const float*)d_in[8];

    float* hemb = (float*)d_out;
    float* flat = (float*)d_out + (size_t)N_NODES * FDIM;

    const int* src = ei;
    const int* dst = ei + N_EDGES;

    __half2* dXh;
    cudaGetSymbolAddress((void**)&dXh, g_xh);
    __half2* dH;
    cudaGetSymbolAddress((void**)&dH, g_h16);
    __half2* h1 = dH;
    __half2* h2 = dH + (size_t)N_NODES * FDIM / 2;
    __half2* h3 = dH + 2 * ((size_t)N_NODES * FDIM / 2);
    float* dOut;
    cudaGetSymbolAddress((void**)&dOut, g_out);

    const int EB = (N_EDGES + 255) / 256;

    // zero scratch + fp16 x copy (fused), then CSR build (by dst)
    zx_kernel<<<SCAN_BLOCKS, 1024>>>(x, flat);
    deg_hist_kernel<<<EB, 256>>>(dst, ew);
    dis_scanA_kernel<<<SCAN_BLOCKS, 1024>>>();
    scanB_kernel<<<1, 128>>>();
    scanC_kernel<<<SCAN_BLOCKS, 1024>>>();
    fill_kernel<<<EB, 256>>>(src, dst, ew);

    // 3 propagation hops (fp16 gather, fp32 accumulate)
    hop_kernel<<<N_NODES / 8, 256>>>(dXh, h1);
    hop_kernel<<<N_NODES / 8, 256>>>(h1,  h2);
    hop_kernel<<<N_NODES / 8, 256>>>(h2,  h3);

    // tensor-core GEMM: out = [xh|h1|h2|h3] @ W + b
    gemm_hmma_kernel<<<(N_NODES + 127) / 128, 256>>>(
        (const __half*)dXh, (const __half*)h1, (const __half*)h2,
        (const __half*)h3, W, b, dOut);

    // GraphNorm + residual ReLU + pooling (finalize inlined into apply)
    stats_kernel<<<N_GRAPHS * NCHUNK, 256>>>(dOut, batch);
    apply_pool_kernel<<<N_GRAPHS * NCHUNK, 256>>>(dOut, x, batch, gw, gb, gms,
                                                  hemb, flat);
}